// round 1
// baseline (speedup 1.0000x reference)
#include <cuda_runtime.h>
#include <math.h>

// Problem constants
#define BB 4
#define HH 16
#define TT 1024
#define DD 64
#define EE 1024
#define MM 4096  // B*T

// Scratch (static device globals — allowed; no runtime allocation)
__device__ float g_q[(size_t)BB*HH*TT*DD];
__device__ float g_k[(size_t)BB*HH*TT*DD];
__device__ float g_v[(size_t)BB*HH*TT*DD];
__device__ float g_o[(size_t)BB*HH*TT*DD];
__device__ float g_s[(size_t)BB*HH*TT*TT];   // 256 MB scores/attn buffer

// ---------------------------------------------------------------------------
// Kernel 1: fused QKV projection.
// C[m, n] = sum_e x[m,e] * W[n,e] + bias[n], scattered into [B,H,T,D] layout.
// TN GEMM, 128x128 tile, BK=8, 256 threads, 8x8 per-thread micro-tile.
// grid: (M/128=32, 3072/128=24)
// ---------------------------------------------------------------------------
__global__ __launch_bounds__(256) void qkv_kernel(
    const float* __restrict__ x,
    const float* __restrict__ Wq, const float* __restrict__ bq,
    const float* __restrict__ Wk, const float* __restrict__ bk,
    const float* __restrict__ Wv, const float* __restrict__ bv)
{
    __shared__ float As[8][128];
    __shared__ float Bs[8][128];
    const int tid = threadIdx.x;
    const int m0 = blockIdx.x * 128;
    const int n0 = blockIdx.y * 128;
    const int which = n0 >> 10;       // 0=q, 1=k, 2=v (128-tile never straddles)
    const int nW = n0 & 1023;

    const float* W;
    const float* bias;
    float* dst;
    if (which == 0)      { W = Wq; bias = bq; dst = g_q; }
    else if (which == 1) { W = Wk; bias = bk; dst = g_k; }
    else                 { W = Wv; bias = bv; dst = g_v; }

    const int lrow = tid >> 1;         // 0..127
    const int lcol = (tid & 1) * 4;    // 0 or 4
    const int ty = tid >> 4;           // 0..15
    const int tx = tid & 15;           // 0..15

    float acc[8][8];
    #pragma unroll
    for (int i = 0; i < 8; i++)
        #pragma unroll
        for (int j = 0; j < 8; j++) acc[i][j] = 0.f;

    for (int k0 = 0; k0 < 1024; k0 += 8) {
        float4 a4 = *(const float4*)(x + (size_t)(m0 + lrow) * 1024 + k0 + lcol);
        float4 b4 = *(const float4*)(W + (size_t)(nW + lrow) * 1024 + k0 + lcol);
        __syncthreads();
        As[lcol + 0][lrow] = a4.x; As[lcol + 1][lrow] = a4.y;
        As[lcol + 2][lrow] = a4.z; As[lcol + 3][lrow] = a4.w;
        Bs[lcol + 0][lrow] = b4.x; Bs[lcol + 1][lrow] = b4.y;
        Bs[lcol + 2][lrow] = b4.z; Bs[lcol + 3][lrow] = b4.w;
        __syncthreads();
        #pragma unroll
        for (int kk = 0; kk < 8; kk++) {
            float ra[8], rb[8];
            #pragma unroll
            for (int i = 0; i < 8; i++) ra[i] = As[kk][ty * 8 + i];
            #pragma unroll
            for (int j = 0; j < 8; j++) rb[j] = Bs[kk][tx * 8 + j];
            #pragma unroll
            for (int i = 0; i < 8; i++)
                #pragma unroll
                for (int j = 0; j < 8; j++)
                    acc[i][j] = fmaf(ra[i], rb[j], acc[i][j]);
        }
    }

    // Scatter epilogue: [m, f] -> [b, h, t, d]
    #pragma unroll
    for (int i = 0; i < 8; i++) {
        int m = m0 + ty * 8 + i;
        int b = m >> 10, t = m & 1023;
        #pragma unroll
        for (int j = 0; j < 8; j++) {
            int f = nW + tx * 8 + j;
            int h = f >> 6, d = f & 63;
            dst[(((size_t)(b * HH + h)) * TT + t) * DD + d] = acc[i][j] + bias[f];
        }
    }
}

// ---------------------------------------------------------------------------
// Kernel 2: scores = scale * q @ k^T per (b,h).
// TN GEMM, K=64.  grid: (8, 8, 64)
// ---------------------------------------------------------------------------
__global__ __launch_bounds__(256) void scores_kernel()
{
    __shared__ float As[8][128];
    __shared__ float Bs[8][128];
    const int tid = threadIdx.x;
    const int m0 = blockIdx.x * 128;
    const int n0 = blockIdx.y * 128;
    const int bh = blockIdx.z;
    const float* q = g_q + (size_t)bh * TT * DD;
    const float* k = g_k + (size_t)bh * TT * DD;
    float* s = g_s + (size_t)bh * TT * TT;

    const int lrow = tid >> 1;
    const int lcol = (tid & 1) * 4;
    const int ty = tid >> 4;
    const int tx = tid & 15;

    float acc[8][8];
    #pragma unroll
    for (int i = 0; i < 8; i++)
        #pragma unroll
        for (int j = 0; j < 8; j++) acc[i][j] = 0.f;

    for (int k0 = 0; k0 < 64; k0 += 8) {
        float4 a4 = *(const float4*)(q + (size_t)(m0 + lrow) * 64 + k0 + lcol);
        float4 b4 = *(const float4*)(k + (size_t)(n0 + lrow) * 64 + k0 + lcol);
        __syncthreads();
        As[lcol + 0][lrow] = a4.x; As[lcol + 1][lrow] = a4.y;
        As[lcol + 2][lrow] = a4.z; As[lcol + 3][lrow] = a4.w;
        Bs[lcol + 0][lrow] = b4.x; Bs[lcol + 1][lrow] = b4.y;
        Bs[lcol + 2][lrow] = b4.z; Bs[lcol + 3][lrow] = b4.w;
        __syncthreads();
        #pragma unroll
        for (int kk = 0; kk < 8; kk++) {
            float ra[8], rb[8];
            #pragma unroll
            for (int i = 0; i < 8; i++) ra[i] = As[kk][ty * 8 + i];
            #pragma unroll
            for (int j = 0; j < 8; j++) rb[j] = Bs[kk][tx * 8 + j];
            #pragma unroll
            for (int i = 0; i < 8; i++)
                #pragma unroll
                for (int j = 0; j < 8; j++)
                    acc[i][j] = fmaf(ra[i], rb[j], acc[i][j]);
        }
    }

    const float scale = 0.125f;  // 1/sqrt(64)
    #pragma unroll
    for (int i = 0; i < 8; i++) {
        size_t r = (size_t)(m0 + ty * 8 + i) * 1024;
        #pragma unroll
        for (int j = 0; j < 8; j++)
            s[r + n0 + tx * 8 + j] = acc[i][j] * scale;
    }
}

// ---------------------------------------------------------------------------
// Kernel 3: row softmax + entropy dropout, in place on g_s.
// Per-head bias cancels in softmax (constant along s axis) -> skipped.
// grid: 65536 blocks of 256 threads; 4 elements/thread.
// ---------------------------------------------------------------------------
__global__ __launch_bounds__(256) void softmax_kernel(
    const float* __restrict__ noise, const float* __restrict__ theta)
{
    __shared__ float red[8];
    const int row = blockIdx.x;
    const int tid = threadIdx.x;
    float* s = g_s + (size_t)row * 1024;
    const float* nz = noise + (size_t)row * 1024;

    // T_mean = mean_h |sin(2 * sigmoid(theta_h) * pi/2)|
    float Tm = 0.f;
    #pragma unroll
    for (int h = 0; h < 16; h++) {
        float th = theta[h];
        float sg = 1.f / (1.f + expf(-th));
        Tm += fabsf(sinf(2.f * sg * 1.57079632679489662f));
    }
    Tm *= (1.f / 16.f);
    const float inv_keep = 1.f / (1.f - Tm + 1e-8f);

    float v[4];
    #pragma unroll
    for (int i = 0; i < 4; i++) v[i] = s[tid + i * 256];

    float mx = fmaxf(fmaxf(v[0], v[1]), fmaxf(v[2], v[3]));
    #pragma unroll
    for (int o = 16; o > 0; o >>= 1)
        mx = fmaxf(mx, __shfl_xor_sync(0xffffffffu, mx, o));
    if ((tid & 31) == 0) red[tid >> 5] = mx;
    __syncthreads();
    mx = red[0];
    #pragma unroll
    for (int i = 1; i < 8; i++) mx = fmaxf(mx, red[i]);
    __syncthreads();

    float e[4], lsum = 0.f;
    #pragma unroll
    for (int i = 0; i < 4; i++) { e[i] = expf(v[i] - mx); lsum += e[i]; }
    #pragma unroll
    for (int o = 16; o > 0; o >>= 1)
        lsum += __shfl_xor_sync(0xffffffffu, lsum, o);
    if ((tid & 31) == 0) red[tid >> 5] = lsum;
    __syncthreads();
    float total = 0.f;
    #pragma unroll
    for (int i = 0; i < 8; i++) total += red[i];
    const float invsum = 1.f / total;

    #pragma unroll
    for (int i = 0; i < 4; i++) {
        int idx = tid + i * 256;
        float keep = (nz[idx] > Tm) ? inv_keep : 0.f;
        s[idx] = e[i] * invsum * keep;
    }
}

// ---------------------------------------------------------------------------
// Kernel 4: out = attn @ v per (b,h). NN GEMM M=1024,N=64,K=1024.
// 128x64 tile, BK=16, 256 threads, 8x4 micro-tile. grid: (8, 1, 64)
// ---------------------------------------------------------------------------
__global__ __launch_bounds__(256) void av_kernel()
{
    __shared__ float As[16][128];
    __shared__ float Bs[16][64];
    const int tid = threadIdx.x;
    const int m0 = blockIdx.x * 128;
    const int bh = blockIdx.z;
    const float* a = g_s + (size_t)bh * TT * TT;
    const float* v = g_v + (size_t)bh * TT * DD;
    float* o = g_o + (size_t)bh * TT * DD;

    const int arow = tid >> 1;           // 0..127
    const int acol = (tid & 1) * 8;      // 0 or 8
    const int brow = tid >> 4;           // 0..15
    const int bcol = (tid & 15) * 4;     // 0..60
    const int ty = tid >> 4;             // rows ty*8
    const int tx = tid & 15;             // cols tx*4

    float acc[8][4];
    #pragma unroll
    for (int i = 0; i < 8; i++)
        #pragma unroll
        for (int j = 0; j < 4; j++) acc[i][j] = 0.f;

    for (int k0 = 0; k0 < 1024; k0 += 16) {
        const float* ap = a + (size_t)(m0 + arow) * 1024 + k0 + acol;
        float4 a40 = *(const float4*)(ap);
        float4 a41 = *(const float4*)(ap + 4);
        float4 b4  = *(const float4*)(v + (size_t)(k0 + brow) * 64 + bcol);
        __syncthreads();
        As[acol + 0][arow] = a40.x; As[acol + 1][arow] = a40.y;
        As[acol + 2][arow] = a40.z; As[acol + 3][arow] = a40.w;
        As[acol + 4][arow] = a41.x; As[acol + 5][arow] = a41.y;
        As[acol + 6][arow] = a41.z; As[acol + 7][arow] = a41.w;
        Bs[brow][bcol + 0] = b4.x; Bs[brow][bcol + 1] = b4.y;
        Bs[brow][bcol + 2] = b4.z; Bs[brow][bcol + 3] = b4.w;
        __syncthreads();
        #pragma unroll
        for (int kk = 0; kk < 16; kk++) {
            float ra[8], rb[4];
            #pragma unroll
            for (int i = 0; i < 8; i++) ra[i] = As[kk][ty * 8 + i];
            #pragma unroll
            for (int j = 0; j < 4; j++) rb[j] = Bs[kk][tx * 4 + j];
            #pragma unroll
            for (int i = 0; i < 8; i++)
                #pragma unroll
                for (int j = 0; j < 4; j++)
                    acc[i][j] = fmaf(ra[i], rb[j], acc[i][j]);
        }
    }

    #pragma unroll
    for (int i = 0; i < 8; i++) {
        size_t r = (size_t)(m0 + ty * 8 + i) * 64;
        #pragma unroll
        for (int j = 0; j < 4; j++)
            o[r + tx * 4 + j] = acc[i][j];
    }
}

// ---------------------------------------------------------------------------
// Kernel 5: output projection with gather from [B,H,T,D].
// C[m,f] = sum_e o'[m,e] * Wo[f,e] + bo[f].  grid: (32, 8)
// ---------------------------------------------------------------------------
__global__ __launch_bounds__(256) void outproj_kernel(
    const float* __restrict__ Wo, const float* __restrict__ bo,
    float* __restrict__ out)
{
    __shared__ float As[8][128];
    __shared__ float Bs[8][128];
    const int tid = threadIdx.x;
    const int m0 = blockIdx.x * 128;
    const int n0 = blockIdx.y * 128;

    const int lrow = tid >> 1;
    const int lcol = (tid & 1) * 4;
    const int ty = tid >> 4;
    const int tx = tid & 15;

    const int m = m0 + lrow;
    const int b = m >> 10, t = m & 1023;

    float acc[8][8];
    #pragma unroll
    for (int i = 0; i < 8; i++)
        #pragma unroll
        for (int j = 0; j < 8; j++) acc[i][j] = 0.f;

    for (int k0 = 0; k0 < 1024; k0 += 8) {
        int e = k0 + lcol;
        int h = e >> 6, d = e & 63;
        float4 a4 = *(const float4*)(g_o + (((size_t)(b * HH + h)) * TT + t) * DD + d);
        float4 b4 = *(const float4*)(Wo + (size_t)(n0 + lrow) * 1024 + k0 + lcol);
        __syncthreads();
        As[lcol + 0][lrow] = a4.x; As[lcol + 1][lrow] = a4.y;
        As[lcol + 2][lrow] = a4.z; As[lcol + 3][lrow] = a4.w;
        Bs[lcol + 0][lrow] = b4.x; Bs[lcol + 1][lrow] = b4.y;
        Bs[lcol + 2][lrow] = b4.z; Bs[lcol + 3][lrow] = b4.w;
        __syncthreads();
        #pragma unroll
        for (int kk = 0; kk < 8; kk++) {
            float ra[8], rb[8];
            #pragma unroll
            for (int i = 0; i < 8; i++) ra[i] = As[kk][ty * 8 + i];
            #pragma unroll
            for (int j = 0; j < 8; j++) rb[j] = Bs[kk][tx * 8 + j];
            #pragma unroll
            for (int i = 0; i < 8; i++)
                #pragma unroll
                for (int j = 0; j < 8; j++)
                    acc[i][j] = fmaf(ra[i], rb[j], acc[i][j]);
        }
    }

    #pragma unroll
    for (int i = 0; i < 8; i++) {
        size_t r = (size_t)(m0 + ty * 8 + i) * 1024;
        #pragma unroll
        for (int j = 0; j < 8; j++) {
            int f = n0 + tx * 8 + j;
            out[r + f] = acc[i][j] + bo[f];
        }
    }
}

// ---------------------------------------------------------------------------
extern "C" void kernel_launch(void* const* d_in, const int* in_sizes, int n_in,
                              void* d_out, int out_size)
{
    (void)in_sizes; (void)n_in; (void)out_size;
    const float* x     = (const float*)d_in[0];
    const float* noise = (const float*)d_in[1];
    const float* Wq    = (const float*)d_in[2];
    const float* bq    = (const float*)d_in[3];
    const float* Wk    = (const float*)d_in[4];
    const float* bk    = (const float*)d_in[5];
    const float* Wv    = (const float*)d_in[6];
    const float* bv    = (const float*)d_in[7];
    const float* Wo    = (const float*)d_in[8];
    const float* bo    = (const float*)d_in[9];
    const float* theta = (const float*)d_in[10];
    // d_in[11] = corr_w: unused (per-head bias cancels in softmax)
    float* out = (float*)d_out;

    qkv_kernel<<<dim3(32, 24), 256>>>(x, Wq, bq, Wk, bk, Wv, bv);
    scores_kernel<<<dim3(8, 8, 64), 256>>>();
    softmax_kernel<<<65536, 256>>>(noise, theta);
    av_kernel<<<dim3(8, 1, 64), 256>>>();
    outproj_kernel<<<dim3(32, 8), 256>>>(Wo, bo, out);
}

// round 4
// speedup vs baseline: 1.6147x; 1.6147x over previous
#include <cuda_runtime.h>
#include <cuda_bf16.h>
#include <cstdint>
#include <math.h>

// Problem: B=4, H=16, T=1024, D=64, E=1024, M=B*T=4096, BH=64
// All GEMMs are TN (C[m,n] = sum_k A[m,k]*B[n,k]) on bf16x2 split planes.

// ---------------------------------------------------------------------------
// Device-global scratch (no runtime allocation allowed)
// ---------------------------------------------------------------------------
__device__ __nv_bfloat16 g_xs0[4194304], g_xs1[4194304];   // x split   [4096][1024]
__device__ __nv_bfloat16 g_wb0[3145728], g_wb1[3145728];   // Wq|Wk|Wv  [3072][1024]
__device__ __nv_bfloat16 g_wo0[1048576], g_wo1[1048576];   // Wo        [1024][1024]
__device__ __nv_bfloat16 g_q0[4194304],  g_q1[4194304];    // q  [bh][t][d]
__device__ __nv_bfloat16 g_k0[4194304],  g_k1[4194304];    // k  [bh][s][d]
__device__ __nv_bfloat16 g_vt0[4194304], g_vt1[4194304];   // vT [bh][d][s]
__device__ float         g_s[67108864];                    // scores [bh][t][s]
__device__ __nv_bfloat16 g_p0[67108864], g_p1[67108864];   // attn planes [bh][t][s]
__device__ __nv_bfloat16 g_c0[4194304],  g_c1[4194304];    // ctx planes [m][e]

// ---------------------------------------------------------------------------
// PTX helpers (portable: no sm_103a-only features)
// ---------------------------------------------------------------------------
__device__ __forceinline__ uint32_t smem_u32(const void* p) {
    uint32_t a;
    asm("{ .reg .u64 t; cvta.to.shared.u64 t, %1; cvt.u32.u64 %0, t; }" : "=r"(a) : "l"(p));
    return a;
}

__device__ __forceinline__ void ldsm4(uint32_t r[4], uint32_t addr) {
    asm volatile("ldmatrix.sync.aligned.m8n8.x4.shared.b16 {%0,%1,%2,%3}, [%4];"
        : "=r"(r[0]), "=r"(r[1]), "=r"(r[2]), "=r"(r[3]) : "r"(addr));
}

__device__ __forceinline__ void mma_bf16(float* c, const uint32_t* a, const uint32_t* b) {
    asm volatile(
        "mma.sync.aligned.m16n8k16.row.col.f32.bf16.bf16.f32 "
        "{%0,%1,%2,%3}, {%4,%5,%6,%7}, {%8,%9}, {%0,%1,%2,%3};\n"
        : "+f"(c[0]), "+f"(c[1]), "+f"(c[2]), "+f"(c[3])
        : "r"(a[0]), "r"(a[1]), "r"(a[2]), "r"(a[3]), "r"(b[0]), "r"(b[1]));
}

// ---------------------------------------------------------------------------
// Split fp32 -> (hi, lo) bf16 planes.  which: 0 = x planes, 1 = wb, 2 = wo.
// ---------------------------------------------------------------------------
__global__ __launch_bounds__(256) void split2_kernel(
    const float* __restrict__ src, int which, size_t off, int n)
{
    __nv_bfloat16 *d0, *d1;
    if (which == 0)      { d0 = g_xs0; d1 = g_xs1; }
    else if (which == 1) { d0 = g_wb0; d1 = g_wb1; }
    else                 { d0 = g_wo0; d1 = g_wo1; }
    d0 += off; d1 += off;
    for (int i = blockIdx.x * 256 + threadIdx.x; i < n; i += gridDim.x * 256) {
        float a = src[i];
        __nv_bfloat16 h = __float2bfloat16(a);
        d0[i] = h;
        d1[i] = __float2bfloat16(a - __bfloat162float(h));
    }
}

// ---------------------------------------------------------------------------
// Core 128x128 tile GEMM (TN), bf16x2 3-pass, fp32 acc.
// 256 threads = 8 warps as 2(m) x 4(n); warp tile 64x32; micro 16x8.
// A/B pointers pre-offset to tile row 0. Row strides LDA/LDB (elements).
// Both smem arrays use 24-element (48 B) rows: float4 stores stay 16B-aligned
// and both ldmatrix (As) and quad b-fragment reads (Bs) are bank-conflict-free.
// ---------------------------------------------------------------------------
template<int KSTEPS, int LDA, int LDB>
__device__ __forceinline__ void gemm128(
    const __nv_bfloat16* __restrict__ A0, const __nv_bfloat16* __restrict__ A1,
    const __nv_bfloat16* __restrict__ B0, const __nv_bfloat16* __restrict__ B1,
    float acc[4][4][4])
{
    __shared__ __nv_bfloat16 As[2][128][24];
    __shared__ __nv_bfloat16 Bs[2][128][24];

    const int tid = threadIdx.x;
    const int lane = tid & 31;
    const int wid = tid >> 5;
    const int wr = wid >> 2;   // 0..1
    const int wc = wid & 3;    // 0..3
    const int lrow = tid >> 1;
    const int lhalf = tid & 1;

    #pragma unroll
    for (int mt = 0; mt < 4; mt++)
        #pragma unroll
        for (int nt = 0; nt < 4; nt++)
            #pragma unroll
            for (int j = 0; j < 4; j++) acc[mt][nt][j] = 0.f;

    uint32_t aaddr[2][4];
    #pragma unroll
    for (int p = 0; p < 2; p++)
        #pragma unroll
        for (int mt = 0; mt < 4; mt++)
            aaddr[p][mt] = smem_u32(&As[p][wr * 64 + mt * 16 + (lane & 15)][(lane >> 4) * 8]);

    const int brow = wc * 32 + (lane >> 2);
    const char* bp0 = (const char*)&Bs[0][brow][(lane & 3) * 2];
    const char* bp1 = (const char*)&Bs[1][brow][(lane & 3) * 2];

    const char* gA0 = (const char*)(A0 + (size_t)lrow * LDA + lhalf * 8);
    const char* gA1 = (const char*)(A1 + (size_t)lrow * LDA + lhalf * 8);
    const char* gB0 = (const char*)(B0 + (size_t)lrow * LDB + lhalf * 8);
    const char* gB1 = (const char*)(B1 + (size_t)lrow * LDB + lhalf * 8);

    float4 ra0 = *(const float4*)(gA0);
    float4 ra1 = *(const float4*)(gA1);
    float4 rb0 = *(const float4*)(gB0);
    float4 rb1 = *(const float4*)(gB1);

    for (int ks = 0; ks < KSTEPS; ks++) {
        __syncthreads();
        *(float4*)((char*)&As[0][lrow][lhalf * 8]) = ra0;
        *(float4*)((char*)&As[1][lrow][lhalf * 8]) = ra1;
        *(float4*)((char*)&Bs[0][lrow][lhalf * 8]) = rb0;
        *(float4*)((char*)&Bs[1][lrow][lhalf * 8]) = rb1;
        __syncthreads();
        if (ks + 1 < KSTEPS) {
            size_t o = (size_t)(ks + 1) * 32;
            ra0 = *(const float4*)(gA0 + o);
            ra1 = *(const float4*)(gA1 + o);
            rb0 = *(const float4*)(gB0 + o);
            rb1 = *(const float4*)(gB1 + o);
        }
        uint32_t aH[4][4], aL[4][4], bH[4][2], bL[4][2];
        #pragma unroll
        for (int mt = 0; mt < 4; mt++) {
            ldsm4(aH[mt], aaddr[0][mt]);
            ldsm4(aL[mt], aaddr[1][mt]);
        }
        #pragma unroll
        for (int nt = 0; nt < 4; nt++) {
            bH[nt][0] = *(const uint32_t*)(bp0 + nt * 384);
            bH[nt][1] = *(const uint32_t*)(bp0 + nt * 384 + 16);
            bL[nt][0] = *(const uint32_t*)(bp1 + nt * 384);
            bL[nt][1] = *(const uint32_t*)(bp1 + nt * 384 + 16);
        }
        #pragma unroll
        for (int mt = 0; mt < 4; mt++)
            #pragma unroll
            for (int nt = 0; nt < 4; nt++) {
                mma_bf16(acc[mt][nt], aH[mt], bH[nt]);
                mma_bf16(acc[mt][nt], aH[mt], bL[nt]);
                mma_bf16(acc[mt][nt], aL[mt], bH[nt]);
            }
    }
    __syncthreads();
}

// ---------------------------------------------------------------------------
// 128x64 tile variant for attn@V (B has 64 rows). Warps 4(m) x 2(n),
// warp tile 32x32: 2 m-tiles x 4 n-tiles.
// ---------------------------------------------------------------------------
template<int KSTEPS>
__device__ __forceinline__ void gemm_av_tile(
    const __nv_bfloat16* __restrict__ A0, const __nv_bfloat16* __restrict__ A1,
    const __nv_bfloat16* __restrict__ B0, const __nv_bfloat16* __restrict__ B1,
    float acc[2][4][4])
{
    __shared__ __nv_bfloat16 As[2][128][24];
    __shared__ __nv_bfloat16 Bs[2][64][24];

    const int tid = threadIdx.x;
    const int lane = tid & 31;
    const int wid = tid >> 5;
    const int wr = wid >> 1;   // 0..3
    const int wc = wid & 1;    // 0..1
    const int lrow = tid >> 1;
    const int lhalf = tid & 1;
    const int bplane = tid >> 7;        // 0..1
    const int bi = tid & 127;
    const int brow_ld = bi >> 1;
    const int bhalf = bi & 1;

    #pragma unroll
    for (int mt = 0; mt < 2; mt++)
        #pragma unroll
        for (int nt = 0; nt < 4; nt++)
            #pragma unroll
            for (int j = 0; j < 4; j++) acc[mt][nt][j] = 0.f;

    uint32_t aaddr[2][2];
    #pragma unroll
    for (int p = 0; p < 2; p++)
        #pragma unroll
        for (int mt = 0; mt < 2; mt++)
            aaddr[p][mt] = smem_u32(&As[p][wr * 32 + mt * 16 + (lane & 15)][(lane >> 4) * 8]);

    const int brow = wc * 32 + (lane >> 2);
    const char* bp0 = (const char*)&Bs[0][brow][(lane & 3) * 2];
    const char* bp1 = (const char*)&Bs[1][brow][(lane & 3) * 2];

    const char* gA0 = (const char*)(A0 + (size_t)lrow * 1024 + lhalf * 8);
    const char* gA1 = (const char*)(A1 + (size_t)lrow * 1024 + lhalf * 8);
    const char* gB  = (const char*)((bplane ? B1 : B0) + (size_t)brow_ld * 1024 + bhalf * 8);

    float4 ra0 = *(const float4*)(gA0);
    float4 ra1 = *(const float4*)(gA1);
    float4 rb  = *(const float4*)(gB);

    for (int ks = 0; ks < KSTEPS; ks++) {
        __syncthreads();
        *(float4*)((char*)&As[0][lrow][lhalf * 8]) = ra0;
        *(float4*)((char*)&As[1][lrow][lhalf * 8]) = ra1;
        *(float4*)((char*)&Bs[bplane][brow_ld][bhalf * 8]) = rb;
        __syncthreads();
        if (ks + 1 < KSTEPS) {
            size_t o = (size_t)(ks + 1) * 32;
            ra0 = *(const float4*)(gA0 + o);
            ra1 = *(const float4*)(gA1 + o);
            rb  = *(const float4*)(gB + o);
        }
        uint32_t aH[2][4], aL[2][4], bH[4][2], bL[4][2];
        #pragma unroll
        for (int mt = 0; mt < 2; mt++) {
            ldsm4(aH[mt], aaddr[0][mt]);
            ldsm4(aL[mt], aaddr[1][mt]);
        }
        #pragma unroll
        for (int nt = 0; nt < 4; nt++) {
            bH[nt][0] = *(const uint32_t*)(bp0 + nt * 384);
            bH[nt][1] = *(const uint32_t*)(bp0 + nt * 384 + 16);
            bL[nt][0] = *(const uint32_t*)(bp1 + nt * 384);
            bL[nt][1] = *(const uint32_t*)(bp1 + nt * 384 + 16);
        }
        #pragma unroll
        for (int mt = 0; mt < 2; mt++)
            #pragma unroll
            for (int nt = 0; nt < 4; nt++) {
                mma_bf16(acc[mt][nt], aH[mt], bH[nt]);
                mma_bf16(acc[mt][nt], aH[mt], bL[nt]);
                mma_bf16(acc[mt][nt], aL[mt], bH[nt]);
            }
    }
    __syncthreads();
}

// ---------------------------------------------------------------------------
// QKV projection. grid (32, 24). Epilogue: bias add, bf16x2 split, scatter
// to q/k [bh][t][d] planes and vT [bh][d][t] planes.
// ---------------------------------------------------------------------------
__global__ __launch_bounds__(256) void qkv_mma_kernel(
    const float* __restrict__ bq, const float* __restrict__ bk,
    const float* __restrict__ bv)
{
    const int m0 = blockIdx.x * 128;
    const int n0 = blockIdx.y * 128;
    float acc[4][4][4];
    gemm128<64, 1024, 1024>(
        g_xs0 + (size_t)m0 * 1024, g_xs1 + (size_t)m0 * 1024,
        g_wb0 + (size_t)n0 * 1024, g_wb1 + (size_t)n0 * 1024, acc);

    const int which = n0 >> 10;
    const int fbase = n0 & 1023;
    const float* bias = (which == 0) ? bq : (which == 1) ? bk : bv;

    const int tid = threadIdx.x, lane = tid & 31, wid = tid >> 5;
    const int wr = wid >> 2, wc = wid & 3;

    #pragma unroll
    for (int mt = 0; mt < 4; mt++) {
        #pragma unroll
        for (int nt = 0; nt < 4; nt++) {
            int f = fbase + wc * 32 + nt * 8 + (lane & 3) * 2;
            int h = f >> 6, d = f & 63;
            float bz0 = bias[f], bz1 = bias[f + 1];
            #pragma unroll
            for (int half = 0; half < 2; half++) {
                int m = m0 + wr * 64 + mt * 16 + (lane >> 2) + half * 8;
                int b = m >> 10, t = m & 1023;
                float v0 = acc[mt][nt][half * 2 + 0] + bz0;
                float v1 = acc[mt][nt][half * 2 + 1] + bz1;
                __nv_bfloat16 h0 = __float2bfloat16(v0);
                __nv_bfloat16 h1 = __float2bfloat16(v1);
                __nv_bfloat16 l0 = __float2bfloat16(v0 - __bfloat162float(h0));
                __nv_bfloat16 l1 = __float2bfloat16(v1 - __bfloat162float(h1));
                if (which < 2) {
                    size_t idx = (((size_t)(b * 16 + h)) * 1024 + t) * 64 + d;
                    __nv_bfloat162 ph; ph.x = h0; ph.y = h1;
                    __nv_bfloat162 pl; pl.x = l0; pl.y = l1;
                    if (which == 0) {
                        *(__nv_bfloat162*)&g_q0[idx] = ph;
                        *(__nv_bfloat162*)&g_q1[idx] = pl;
                    } else {
                        *(__nv_bfloat162*)&g_k0[idx] = ph;
                        *(__nv_bfloat162*)&g_k1[idx] = pl;
                    }
                } else {
                    size_t base = ((size_t)(b * 16 + h) * 64 + d) * 1024 + t;
                    g_vt0[base] = h0;        g_vt1[base] = l0;
                    g_vt0[base + 1024] = h1; g_vt1[base + 1024] = l1;
                }
            }
        }
    }
}

// ---------------------------------------------------------------------------
// Scores: s = 0.125 * q @ k^T per bh. grid (8, 8, 64). K=64 (4 k-steps).
// ---------------------------------------------------------------------------
__global__ __launch_bounds__(256) void scores_mma_kernel()
{
    const int m0 = blockIdx.x * 128;
    const int n0 = blockIdx.y * 128;
    const int bh = blockIdx.z;
    const size_t off = (size_t)bh * 65536;
    float acc[4][4][4];
    gemm128<4, 64, 64>(
        g_q0 + off + (size_t)m0 * 64, g_q1 + off + (size_t)m0 * 64,
        g_k0 + off + (size_t)n0 * 64, g_k1 + off + (size_t)n0 * 64, acc);

    float* s = g_s + (size_t)bh * 1048576;
    const int tid = threadIdx.x, lane = tid & 31, wid = tid >> 5;
    const int wr = wid >> 2, wc = wid & 3;

    #pragma unroll
    for (int mt = 0; mt < 4; mt++)
        #pragma unroll
        for (int nt = 0; nt < 4; nt++) {
            int n = n0 + wc * 32 + nt * 8 + (lane & 3) * 2;
            #pragma unroll
            for (int half = 0; half < 2; half++) {
                int m = m0 + wr * 64 + mt * 16 + (lane >> 2) + half * 8;
                float2 v;
                v.x = acc[mt][nt][half * 2 + 0] * 0.125f;
                v.y = acc[mt][nt][half * 2 + 1] * 0.125f;
                *(float2*)&s[(size_t)m * 1024 + n] = v;
            }
        }
}

// ---------------------------------------------------------------------------
// Softmax + entropy dropout; writes attn bf16x2 planes.
// Per-head bias cancels in softmax (constant along s) -> skipped.
// ---------------------------------------------------------------------------
__global__ __launch_bounds__(256) void softmax_kernel(
    const float* __restrict__ noise, const float* __restrict__ theta)
{
    __shared__ float red[8];
    const int row = blockIdx.x;
    const int tid = threadIdx.x;
    const float* s = g_s + (size_t)row * 1024;
    const float* nz = noise + (size_t)row * 1024;

    float Tm = 0.f;
    #pragma unroll
    for (int h = 0; h < 16; h++) {
        float th = theta[h];
        float sg = 1.f / (1.f + expf(-th));
        Tm += fabsf(sinf(2.f * sg * 1.57079632679489662f));
    }
    Tm *= (1.f / 16.f);
    const float inv_keep = 1.f / (1.f - Tm + 1e-8f);

    float v[4];
    #pragma unroll
    for (int i = 0; i < 4; i++) v[i] = s[tid + i * 256];

    float mx = fmaxf(fmaxf(v[0], v[1]), fmaxf(v[2], v[3]));
    #pragma unroll
    for (int o = 16; o > 0; o >>= 1)
        mx = fmaxf(mx, __shfl_xor_sync(0xffffffffu, mx, o));
    if ((tid & 31) == 0) red[tid >> 5] = mx;
    __syncthreads();
    mx = red[0];
    #pragma unroll
    for (int i = 1; i < 8; i++) mx = fmaxf(mx, red[i]);
    __syncthreads();

    float e[4], lsum = 0.f;
    #pragma unroll
    for (int i = 0; i < 4; i++) { e[i] = expf(v[i] - mx); lsum += e[i]; }
    #pragma unroll
    for (int o = 16; o > 0; o >>= 1)
        lsum += __shfl_xor_sync(0xffffffffu, lsum, o);
    if ((tid & 31) == 0) red[tid >> 5] = lsum;
    __syncthreads();
    float total = 0.f;
    #pragma unroll
    for (int i = 0; i < 8; i++) total += red[i];
    const float invsum = 1.f / total;

    #pragma unroll
    for (int i = 0; i < 4; i++) {
        int idx = tid + i * 256;
        float keep = (nz[idx] > Tm) ? inv_keep : 0.f;
        float p = e[i] * invsum * keep;
        __nv_bfloat16 hi = __float2bfloat16(p);
        size_t g = (size_t)row * 1024 + idx;
        g_p0[g] = hi;
        g_p1[g] = __float2bfloat16(p - __bfloat162float(hi));
    }
}

// ---------------------------------------------------------------------------
// attn @ V per bh. grid (8, 64). Epilogue writes ctx bf16x2 planes in [m,e].
// ---------------------------------------------------------------------------
__global__ __launch_bounds__(256) void av_mma_kernel()
{
    const int m0 = blockIdx.x * 128;
    const int bh = blockIdx.y;
    float acc[2][4][4];
    gemm_av_tile<64>(
        g_p0 + (size_t)bh * 1048576 + (size_t)m0 * 1024,
        g_p1 + (size_t)bh * 1048576 + (size_t)m0 * 1024,
        g_vt0 + (size_t)bh * 65536, g_vt1 + (size_t)bh * 65536, acc);

    const int b = bh >> 4, h = bh & 15;
    const int tid = threadIdx.x, lane = tid & 31, wid = tid >> 5;
    const int wr = wid >> 1, wc = wid & 1;

    #pragma unroll
    for (int mt = 0; mt < 2; mt++)
        #pragma unroll
        for (int nt = 0; nt < 4; nt++) {
            int d = wc * 32 + nt * 8 + (lane & 3) * 2;
            #pragma unroll
            for (int half = 0; half < 2; half++) {
                int t = m0 + wr * 32 + mt * 16 + (lane >> 2) + half * 8;
                float v0 = acc[mt][nt][half * 2 + 0];
                float v1 = acc[mt][nt][half * 2 + 1];
                __nv_bfloat16 h0 = __float2bfloat16(v0);
                __nv_bfloat16 h1 = __float2bfloat16(v1);
                __nv_bfloat16 l0 = __float2bfloat16(v0 - __bfloat162float(h0));
                __nv_bfloat16 l1 = __float2bfloat16(v1 - __bfloat162float(h1));
                size_t idx = ((size_t)b * 1024 + t) * 1024 + h * 64 + d;
                __nv_bfloat162 ph; ph.x = h0; ph.y = h1;
                __nv_bfloat162 pl; pl.x = l0; pl.y = l1;
                *(__nv_bfloat162*)&g_c0[idx] = ph;
                *(__nv_bfloat162*)&g_c1[idx] = pl;
            }
        }
}

// ---------------------------------------------------------------------------
// Output projection. grid (32, 8). out = ctx @ Wo^T + bo (fp32 out).
// ---------------------------------------------------------------------------
__global__ __launch_bounds__(256) void outproj_mma_kernel(
    const float* __restrict__ bo, float* __restrict__ out)
{
    const int m0 = blockIdx.x * 128;
    const int n0 = blockIdx.y * 128;
    float acc[4][4][4];
    gemm128<64, 1024, 1024>(
        g_c0 + (size_t)m0 * 1024, g_c1 + (size_t)m0 * 1024,
        g_wo0 + (size_t)n0 * 1024, g_wo1 + (size_t)n0 * 1024, acc);

    const int tid = threadIdx.x, lane = tid & 31, wid = tid >> 5;
    const int wr = wid >> 2, wc = wid & 3;

    #pragma unroll
    for (int mt = 0; mt < 4; mt++)
        #pragma unroll
        for (int nt = 0; nt < 4; nt++) {
            int f = n0 + wc * 32 + nt * 8 + (lane & 3) * 2;
            float bz0 = bo[f], bz1 = bo[f + 1];
            #pragma unroll
            for (int half = 0; half < 2; half++) {
                int m = m0 + wr * 64 + mt * 16 + (lane >> 2) + half * 8;
                float2 v;
                v.x = acc[mt][nt][half * 2 + 0] + bz0;
                v.y = acc[mt][nt][half * 2 + 1] + bz1;
                *(float2*)&out[(size_t)m * 1024 + f] = v;
            }
        }
}

// ---------------------------------------------------------------------------
extern "C" void kernel_launch(void* const* d_in, const int* in_sizes, int n_in,
                              void* d_out, int out_size)
{
    (void)in_sizes; (void)n_in; (void)out_size;
    const float* x     = (const float*)d_in[0];
    const float* noise = (const float*)d_in[1];
    const float* Wq    = (const float*)d_in[2];
    const float* bq    = (const float*)d_in[3];
    const float* Wk    = (const float*)d_in[4];
    const float* bk    = (const float*)d_in[5];
    const float* Wv    = (const float*)d_in[6];
    const float* bv    = (const float*)d_in[7];
    const float* Wo    = (const float*)d_in[8];
    const float* bo    = (const float*)d_in[9];
    const float* theta = (const float*)d_in[10];
    // d_in[11] = corr_w: unused (per-head bias cancels in softmax)
    float* out = (float*)d_out;

    split2_kernel<<<1024, 256>>>(x,  0, 0,       4194304);
    split2_kernel<<<512,  256>>>(Wq, 1, 0,       1048576);
    split2_kernel<<<512,  256>>>(Wk, 1, 1048576, 1048576);
    split2_kernel<<<512,  256>>>(Wv, 1, 2097152, 1048576);
    split2_kernel<<<512,  256>>>(Wo, 2, 0,       1048576);

    qkv_mma_kernel<<<dim3(32, 24), 256>>>(bq, bk, bv);
    scores_mma_kernel<<<dim3(8, 8, 64), 256>>>();
    softmax_kernel<<<65536, 256>>>(noise, theta);
    av_mma_kernel<<<dim3(8, 64), 256>>>();
    outproj_mma_kernel<<<dim3(32, 8), 256>>>(bo, out);
}

// round 5
// speedup vs baseline: 2.4179x; 1.4974x over previous
#include <cuda_runtime.h>
#include <cuda_bf16.h>
#include <cstdint>
#include <math.h>

// Problem: B=4, H=16, T=1024, D=64, E=1024, M=B*T=4096, BH=64
// GEMMs are TN (C[m,n] = sum_k A[m,k]*B[n,k]) on bf16x2 split planes.

// ---------------------------------------------------------------------------
// Device-global scratch
// ---------------------------------------------------------------------------
__device__ __nv_bfloat16 g_xs0[4194304], g_xs1[4194304];   // x split   [4096][1024]
__device__ __nv_bfloat16 g_wb0[3145728], g_wb1[3145728];   // Wq|Wk|Wv  [3072][1024]
__device__ __nv_bfloat16 g_wo0[1048576], g_wo1[1048576];   // Wo        [1024][1024]
__device__ __nv_bfloat16 g_q0[4194304],  g_q1[4194304];    // q (pre-scaled 1/8) [bh][t][d]
__device__ __nv_bfloat16 g_k0[4194304],  g_k1[4194304];    // k  [bh][s][d]
__device__ __nv_bfloat16 g_vt0[4194304], g_vt1[4194304];   // vT [bh][d][s]
__device__ __nv_bfloat16 g_c0[4194304],  g_c1[4194304];    // ctx planes [m][e]

// ---------------------------------------------------------------------------
// PTX helpers (portable: no sm_103a-only features)
// ---------------------------------------------------------------------------
__device__ __forceinline__ uint32_t smem_u32(const void* p) {
    uint32_t a;
    asm("{ .reg .u64 t; cvta.to.shared.u64 t, %1; cvt.u32.u64 %0, t; }" : "=r"(a) : "l"(p));
    return a;
}

__device__ __forceinline__ void ldsm4(uint32_t r[4], uint32_t addr) {
    asm volatile("ldmatrix.sync.aligned.m8n8.x4.shared.b16 {%0,%1,%2,%3}, [%4];"
        : "=r"(r[0]), "=r"(r[1]), "=r"(r[2]), "=r"(r[3]) : "r"(addr));
}

__device__ __forceinline__ void mma_bf16(float* c, const uint32_t* a, const uint32_t* b) {
    asm volatile(
        "mma.sync.aligned.m16n8k16.row.col.f32.bf16.bf16.f32 "
        "{%0,%1,%2,%3}, {%4,%5,%6,%7}, {%8,%9}, {%0,%1,%2,%3};\n"
        : "+f"(c[0]), "+f"(c[1]), "+f"(c[2]), "+f"(c[3])
        : "r"(a[0]), "r"(a[1]), "r"(a[2]), "r"(a[3]), "r"(b[0]), "r"(b[1]));
}

__device__ __forceinline__ uint32_t pack_hi(float x, float y, float& rx, float& ry) {
    __nv_bfloat162 h;
    h.x = __float2bfloat16(x); h.y = __float2bfloat16(y);
    rx = x - __bfloat162float(h.x);
    ry = y - __bfloat162float(h.y);
    return *(uint32_t*)&h;
}
__device__ __forceinline__ uint32_t pack_bf2(float x, float y) {
    __nv_bfloat162 h;
    h.x = __float2bfloat16(x); h.y = __float2bfloat16(y);
    return *(uint32_t*)&h;
}

// ---------------------------------------------------------------------------
// Split fp32 -> (hi, lo) bf16 planes.  which: 0 = x planes, 1 = wb, 2 = wo.
// ---------------------------------------------------------------------------
__global__ __launch_bounds__(256) void split2_kernel(
    const float* __restrict__ src, int which, size_t off, int n)
{
    __nv_bfloat16 *d0, *d1;
    if (which == 0)      { d0 = g_xs0; d1 = g_xs1; }
    else if (which == 1) { d0 = g_wb0; d1 = g_wb1; }
    else                 { d0 = g_wo0; d1 = g_wo1; }
    d0 += off; d1 += off;
    for (int i = blockIdx.x * 256 + threadIdx.x; i < n; i += gridDim.x * 256) {
        float a = src[i];
        __nv_bfloat16 h = __float2bfloat16(a);
        d0[i] = h;
        d1[i] = __float2bfloat16(a - __bfloat162float(h));
    }
}

// ---------------------------------------------------------------------------
// Core 128x128 tile GEMM (TN), bf16x2 3-pass, fp32 acc. (unchanged from R4)
// ---------------------------------------------------------------------------
template<int KSTEPS, int LDA, int LDB>
__device__ __forceinline__ void gemm128(
    const __nv_bfloat16* __restrict__ A0, const __nv_bfloat16* __restrict__ A1,
    const __nv_bfloat16* __restrict__ B0, const __nv_bfloat16* __restrict__ B1,
    float acc[4][4][4])
{
    __shared__ __nv_bfloat16 As[2][128][24];
    __shared__ __nv_bfloat16 Bs[2][128][24];

    const int tid = threadIdx.x;
    const int lane = tid & 31;
    const int wid = tid >> 5;
    const int wr = wid >> 2;
    const int wc = wid & 3;
    const int lrow = tid >> 1;
    const int lhalf = tid & 1;

    #pragma unroll
    for (int mt = 0; mt < 4; mt++)
        #pragma unroll
        for (int nt = 0; nt < 4; nt++)
            #pragma unroll
            for (int j = 0; j < 4; j++) acc[mt][nt][j] = 0.f;

    uint32_t aaddr[2][4];
    #pragma unroll
    for (int p = 0; p < 2; p++)
        #pragma unroll
        for (int mt = 0; mt < 4; mt++)
            aaddr[p][mt] = smem_u32(&As[p][wr * 64 + mt * 16 + (lane & 15)][(lane >> 4) * 8]);

    const int brow = wc * 32 + (lane >> 2);
    const char* bp0 = (const char*)&Bs[0][brow][(lane & 3) * 2];
    const char* bp1 = (const char*)&Bs[1][brow][(lane & 3) * 2];

    const char* gA0 = (const char*)(A0 + (size_t)lrow * LDA + lhalf * 8);
    const char* gA1 = (const char*)(A1 + (size_t)lrow * LDA + lhalf * 8);
    const char* gB0 = (const char*)(B0 + (size_t)lrow * LDB + lhalf * 8);
    const char* gB1 = (const char*)(B1 + (size_t)lrow * LDB + lhalf * 8);

    float4 ra0 = *(const float4*)(gA0);
    float4 ra1 = *(const float4*)(gA1);
    float4 rb0 = *(const float4*)(gB0);
    float4 rb1 = *(const float4*)(gB1);

    for (int ks = 0; ks < KSTEPS; ks++) {
        __syncthreads();
        *(float4*)((char*)&As[0][lrow][lhalf * 8]) = ra0;
        *(float4*)((char*)&As[1][lrow][lhalf * 8]) = ra1;
        *(float4*)((char*)&Bs[0][lrow][lhalf * 8]) = rb0;
        *(float4*)((char*)&Bs[1][lrow][lhalf * 8]) = rb1;
        __syncthreads();
        if (ks + 1 < KSTEPS) {
            size_t o = (size_t)(ks + 1) * 32;
            ra0 = *(const float4*)(gA0 + o);
            ra1 = *(const float4*)(gA1 + o);
            rb0 = *(const float4*)(gB0 + o);
            rb1 = *(const float4*)(gB1 + o);
        }
        uint32_t aH[4][4], aL[4][4], bH[4][2], bL[4][2];
        #pragma unroll
        for (int mt = 0; mt < 4; mt++) {
            ldsm4(aH[mt], aaddr[0][mt]);
            ldsm4(aL[mt], aaddr[1][mt]);
        }
        #pragma unroll
        for (int nt = 0; nt < 4; nt++) {
            bH[nt][0] = *(const uint32_t*)(bp0 + nt * 384);
            bH[nt][1] = *(const uint32_t*)(bp0 + nt * 384 + 16);
            bL[nt][0] = *(const uint32_t*)(bp1 + nt * 384);
            bL[nt][1] = *(const uint32_t*)(bp1 + nt * 384 + 16);
        }
        #pragma unroll
        for (int mt = 0; mt < 4; mt++)
            #pragma unroll
            for (int nt = 0; nt < 4; nt++) {
                mma_bf16(acc[mt][nt], aH[mt], bH[nt]);
                mma_bf16(acc[mt][nt], aH[mt], bL[nt]);
                mma_bf16(acc[mt][nt], aL[mt], bH[nt]);
            }
    }
    __syncthreads();
}

// ---------------------------------------------------------------------------
// QKV projection. grid (32, 24). q is pre-scaled by 0.125 (exact pow2).
// ---------------------------------------------------------------------------
__global__ __launch_bounds__(256) void qkv_mma_kernel(
    const float* __restrict__ bq, const float* __restrict__ bk,
    const float* __restrict__ bv)
{
    const int m0 = blockIdx.x * 128;
    const int n0 = blockIdx.y * 128;
    float acc[4][4][4];
    gemm128<64, 1024, 1024>(
        g_xs0 + (size_t)m0 * 1024, g_xs1 + (size_t)m0 * 1024,
        g_wb0 + (size_t)n0 * 1024, g_wb1 + (size_t)n0 * 1024, acc);

    const int which = n0 >> 10;
    const int fbase = n0 & 1023;
    const float* bias = (which == 0) ? bq : (which == 1) ? bk : bv;
    const float psc = (which == 0) ? 0.125f : 1.0f;

    const int tid = threadIdx.x, lane = tid & 31, wid = tid >> 5;
    const int wr = wid >> 2, wc = wid & 3;

    #pragma unroll
    for (int mt = 0; mt < 4; mt++) {
        #pragma unroll
        for (int nt = 0; nt < 4; nt++) {
            int f = fbase + wc * 32 + nt * 8 + (lane & 3) * 2;
            int h = f >> 6, d = f & 63;
            float bz0 = bias[f], bz1 = bias[f + 1];
            #pragma unroll
            for (int half = 0; half < 2; half++) {
                int m = m0 + wr * 64 + mt * 16 + (lane >> 2) + half * 8;
                int b = m >> 10, t = m & 1023;
                float v0 = (acc[mt][nt][half * 2 + 0] + bz0) * psc;
                float v1 = (acc[mt][nt][half * 2 + 1] + bz1) * psc;
                __nv_bfloat16 h0 = __float2bfloat16(v0);
                __nv_bfloat16 h1 = __float2bfloat16(v1);
                __nv_bfloat16 l0 = __float2bfloat16(v0 - __bfloat162float(h0));
                __nv_bfloat16 l1 = __float2bfloat16(v1 - __bfloat162float(h1));
                if (which < 2) {
                    size_t idx = (((size_t)(b * 16 + h)) * 1024 + t) * 64 + d;
                    __nv_bfloat162 ph; ph.x = h0; ph.y = h1;
                    __nv_bfloat162 pl; pl.x = l0; pl.y = l1;
                    if (which == 0) {
                        *(__nv_bfloat162*)&g_q0[idx] = ph;
                        *(__nv_bfloat162*)&g_q1[idx] = pl;
                    } else {
                        *(__nv_bfloat162*)&g_k0[idx] = ph;
                        *(__nv_bfloat162*)&g_k1[idx] = pl;
                    }
                } else {
                    size_t base = ((size_t)(b * 16 + h) * 64 + d) * 1024 + t;
                    g_vt0[base] = h0;        g_vt1[base] = l0;
                    g_vt0[base + 1024] = h1; g_vt1[base + 1024] = l1;
                }
            }
        }
    }
}

// ---------------------------------------------------------------------------
// Fused flash attention: scores + softmax + dropout + P@V. grid (8, 64).
// 8 warps; warp w owns 16 query rows. Online softmax, all stats warp-local.
// Dynamic smem: Q(2 planes)[128][72] | K(2)[128][72] | Vt(2)[64][136].
// ---------------------------------------------------------------------------
#define FL_Q0 0
#define FL_Q1 18432
#define FL_K0 36864
#define FL_K1 55296
#define FL_V0 73728
#define FL_V1 91136
#define FL_SMEM 108544

__global__ __launch_bounds__(256) void flash_kernel(
    const float* __restrict__ noise, const float* __restrict__ theta)
{
    extern __shared__ char sm[];
    __nv_bfloat16* q0s = (__nv_bfloat16*)(sm + FL_Q0);
    __nv_bfloat16* q1s = (__nv_bfloat16*)(sm + FL_Q1);
    __nv_bfloat16* k0s = (__nv_bfloat16*)(sm + FL_K0);
    __nv_bfloat16* k1s = (__nv_bfloat16*)(sm + FL_K1);
    __nv_bfloat16* v0s = (__nv_bfloat16*)(sm + FL_V0);
    __nv_bfloat16* v1s = (__nv_bfloat16*)(sm + FL_V1);

    const int tid = threadIdx.x;
    const int lane = tid & 31;
    const int wid = tid >> 5;
    const int m0 = blockIdx.x * 128;
    const int bh = blockIdx.y;
    const int bb = bh >> 4, hh = bh & 15;

    // T_mean from theta (exact math: sinf/expf)
    float Tm = 0.f;
    #pragma unroll
    for (int h = 0; h < 16; h++) {
        float sg = 1.f / (1.f + expf(-theta[h]));
        Tm += fabsf(sinf(2.f * sg * 1.57079632679489662f));
    }
    Tm *= (1.f / 16.f);
    const float inv_keep = 1.f / (1.f - Tm + 1e-8f);

    // Load Q tile (stays resident)
    {
        const __nv_bfloat16* gq0 = g_q0 + (size_t)bh * 65536 + (size_t)m0 * 64;
        const __nv_bfloat16* gq1 = g_q1 + (size_t)bh * 65536 + (size_t)m0 * 64;
        #pragma unroll
        for (int i = 0; i < 4; i++) {
            int idx = i * 256 + tid;      // 1024 chunks of 8 bf16
            int row = idx >> 3, c = idx & 7;
            *(float4*)(q0s + row * 72 + c * 8) = *(const float4*)(gq0 + row * 64 + c * 8);
            *(float4*)(q1s + row * 72 + c * 8) = *(const float4*)(gq1 + row * 64 + c * 8);
        }
    }

    // ldmatrix A addresses for this warp's 16 Q rows
    uint32_t qa0 = smem_u32(q0s + (wid * 16 + (lane & 15)) * 72 + (lane >> 4) * 8);
    uint32_t qa1 = smem_u32(q1s + (wid * 16 + (lane & 15)) * 72 + (lane >> 4) * 8);

    // B-fragment base pointers (byte addressed)
    const char* kb0 = (const char*)k0s + (lane >> 2) * 144 + (lane & 3) * 4;
    const char* kb1 = (const char*)k1s + (lane >> 2) * 144 + (lane & 3) * 4;
    const char* vb0 = (const char*)v0s + (lane >> 2) * 272 + (lane & 3) * 4;
    const char* vb1 = (const char*)v1s + (lane >> 2) * 272 + (lane & 3) * 4;

    const __nv_bfloat16* gk0 = g_k0 + (size_t)bh * 65536;
    const __nv_bfloat16* gk1 = g_k1 + (size_t)bh * 65536;
    const __nv_bfloat16* gv0 = g_vt0 + (size_t)bh * 65536;
    const __nv_bfloat16* gv1 = g_vt1 + (size_t)bh * 65536;

    const int row_q = wid * 16 + (lane >> 2);          // local row (first of pair)
    const float* nz_base = noise + (size_t)bh * 1048576
                         + (size_t)(m0 + row_q) * 1024 + (lane & 3) * 2;

    float m_prev0 = -1e30f, m_prev1 = -1e30f;
    float l0 = 0.f, l1 = 0.f;
    float O[8][4];
    #pragma unroll
    for (int nt = 0; nt < 8; nt++)
        #pragma unroll
        for (int j = 0; j < 4; j++) O[nt][j] = 0.f;

    for (int s0 = 0; s0 < 1024; s0 += 128) {
        __syncthreads();   // previous iteration's smem reads done
        // Load K tile [128 keys][64 d] and Vt tile [64 d][128 keys]
        #pragma unroll
        for (int i = 0; i < 4; i++) {
            int idx = i * 256 + tid;
            int row = idx >> 3, c = idx & 7;
            *(float4*)(k0s + row * 72 + c * 8) =
                *(const float4*)(gk0 + (size_t)(s0 + row) * 64 + c * 8);
            *(float4*)(k1s + row * 72 + c * 8) =
                *(const float4*)(gk1 + (size_t)(s0 + row) * 64 + c * 8);
            int vrow = idx >> 4, vc = idx & 15;
            *(float4*)(v0s + vrow * 136 + vc * 8) =
                *(const float4*)(gv0 + (size_t)vrow * 1024 + s0 + vc * 8);
            *(float4*)(v1s + vrow * 136 + vc * 8) =
                *(const float4*)(gv1 + (size_t)vrow * 1024 + s0 + vc * 8);
        }
        __syncthreads();

        // ---- scores: S(16x128) = Qw @ K^T (Q pre-scaled by 1/8) ----
        float Sa[16][4];
        #pragma unroll
        for (int nt = 0; nt < 16; nt++)
            #pragma unroll
            for (int j = 0; j < 4; j++) Sa[nt][j] = 0.f;

        #pragma unroll
        for (int kc = 0; kc < 4; kc++) {
            uint32_t aH[4], aL[4];
            ldsm4(aH, qa0 + kc * 32);
            ldsm4(aL, qa1 + kc * 32);
            #pragma unroll
            for (int nt = 0; nt < 16; nt++) {
                uint32_t bH[2], bL[2];
                bH[0] = *(const uint32_t*)(kb0 + nt * 1152 + kc * 32);
                bH[1] = *(const uint32_t*)(kb0 + nt * 1152 + kc * 32 + 16);
                bL[0] = *(const uint32_t*)(kb1 + nt * 1152 + kc * 32);
                bL[1] = *(const uint32_t*)(kb1 + nt * 1152 + kc * 32 + 16);
                mma_bf16(Sa[nt], aH, bH);
                mma_bf16(Sa[nt], aH, bL);
                mma_bf16(Sa[nt], aL, bH);
            }
        }

        // ---- online softmax (rows lane>>2 and lane>>2+8) ----
        float mt0 = -1e30f, mt1 = -1e30f;
        #pragma unroll
        for (int nt = 0; nt < 16; nt++) {
            mt0 = fmaxf(mt0, fmaxf(Sa[nt][0], Sa[nt][1]));
            mt1 = fmaxf(mt1, fmaxf(Sa[nt][2], Sa[nt][3]));
        }
        mt0 = fmaxf(mt0, __shfl_xor_sync(0xffffffffu, mt0, 1));
        mt0 = fmaxf(mt0, __shfl_xor_sync(0xffffffffu, mt0, 2));
        mt1 = fmaxf(mt1, __shfl_xor_sync(0xffffffffu, mt1, 1));
        mt1 = fmaxf(mt1, __shfl_xor_sync(0xffffffffu, mt1, 2));

        float mn0 = fmaxf(m_prev0, mt0), mn1 = fmaxf(m_prev1, mt1);
        float f0 = __expf(m_prev0 - mn0), f1 = __expf(m_prev1 - mn1);
        m_prev0 = mn0; m_prev1 = mn1;
        l0 *= f0; l1 *= f1;
        #pragma unroll
        for (int nt = 0; nt < 8; nt++) {
            O[nt][0] *= f0; O[nt][1] *= f0;
            O[nt][2] *= f1; O[nt][3] *= f1;
        }

        float rs0 = 0.f, rs1 = 0.f;
        #pragma unroll
        for (int nt = 0; nt < 16; nt++) {
            Sa[nt][0] = __expf(Sa[nt][0] - mn0);
            Sa[nt][1] = __expf(Sa[nt][1] - mn0);
            Sa[nt][2] = __expf(Sa[nt][2] - mn1);
            Sa[nt][3] = __expf(Sa[nt][3] - mn1);
            rs0 += Sa[nt][0] + Sa[nt][1];
            rs1 += Sa[nt][2] + Sa[nt][3];
        }
        rs0 += __shfl_xor_sync(0xffffffffu, rs0, 1);
        rs0 += __shfl_xor_sync(0xffffffffu, rs0, 2);
        rs1 += __shfl_xor_sync(0xffffffffu, rs1, 1);
        rs1 += __shfl_xor_sync(0xffffffffu, rs1, 2);
        l0 += rs0; l1 += rs1;

        // ---- dropout (after denominator accumulation) ----
        const float* nz0 = nz_base + s0;
        #pragma unroll
        for (int nt = 0; nt < 16; nt++) {
            float2 a = *(const float2*)(nz0 + nt * 8);
            float2 b = *(const float2*)(nz0 + 8192 + nt * 8);
            Sa[nt][0] *= (a.x > Tm) ? inv_keep : 0.f;
            Sa[nt][1] *= (a.y > Tm) ? inv_keep : 0.f;
            Sa[nt][2] *= (b.x > Tm) ? inv_keep : 0.f;
            Sa[nt][3] *= (b.y > Tm) ? inv_keep : 0.f;
        }

        // ---- P @ V : C-fragment -> A-fragment identity, hi+lo planes ----
        #pragma unroll
        for (int kc = 0; kc < 8; kc++) {
            uint32_t aPH[4], aPL[4];
            float r0, r1;
            aPH[0] = pack_hi(Sa[2*kc][0],   Sa[2*kc][1],   r0, r1);
            aPL[0] = pack_bf2(r0, r1);
            aPH[1] = pack_hi(Sa[2*kc][2],   Sa[2*kc][3],   r0, r1);
            aPL[1] = pack_bf2(r0, r1);
            aPH[2] = pack_hi(Sa[2*kc+1][0], Sa[2*kc+1][1], r0, r1);
            aPL[2] = pack_bf2(r0, r1);
            aPH[3] = pack_hi(Sa[2*kc+1][2], Sa[2*kc+1][3], r0, r1);
            aPL[3] = pack_bf2(r0, r1);
            #pragma unroll
            for (int nt = 0; nt < 8; nt++) {
                uint32_t vH[2], vL[2];
                vH[0] = *(const uint32_t*)(vb0 + nt * 2176 + kc * 32);
                vH[1] = *(const uint32_t*)(vb0 + nt * 2176 + kc * 32 + 16);
                vL[0] = *(const uint32_t*)(vb1 + nt * 2176 + kc * 32);
                vL[1] = *(const uint32_t*)(vb1 + nt * 2176 + kc * 32 + 16);
                mma_bf16(O[nt], aPH, vH);
                mma_bf16(O[nt], aPH, vL);
                mma_bf16(O[nt], aPL, vH);
            }
        }
    }

    // ---- epilogue: normalize, split, write ctx planes [m][e] ----
    const float il0 = 1.f / l0, il1 = 1.f / l1;
    const int t0 = m0 + row_q;
    #pragma unroll
    for (int nt = 0; nt < 8; nt++) {
        int d = nt * 8 + (lane & 3) * 2;
        #pragma unroll
        for (int half = 0; half < 2; half++) {
            int t = t0 + half * 8;
            float v0 = O[nt][half * 2 + 0] * (half ? il1 : il0);
            float v1 = O[nt][half * 2 + 1] * (half ? il1 : il0);
            __nv_bfloat16 h0 = __float2bfloat16(v0);
            __nv_bfloat16 h1 = __float2bfloat16(v1);
            __nv_bfloat16 lo0 = __float2bfloat16(v0 - __bfloat162float(h0));
            __nv_bfloat16 lo1 = __float2bfloat16(v1 - __bfloat162float(h1));
            size_t idx = ((size_t)bb * 1024 + t) * 1024 + hh * 64 + d;
            __nv_bfloat162 ph; ph.x = h0; ph.y = h1;
            __nv_bfloat162 pl; pl.x = lo0; pl.y = lo1;
            *(__nv_bfloat162*)&g_c0[idx] = ph;
            *(__nv_bfloat162*)&g_c1[idx] = pl;
        }
    }
}

// ---------------------------------------------------------------------------
// Output projection. grid (32, 8). out = ctx @ Wo^T + bo (fp32 out).
// ---------------------------------------------------------------------------
__global__ __launch_bounds__(256) void outproj_mma_kernel(
    const float* __restrict__ bo, float* __restrict__ out)
{
    const int m0 = blockIdx.x * 128;
    const int n0 = blockIdx.y * 128;
    float acc[4][4][4];
    gemm128<64, 1024, 1024>(
        g_c0 + (size_t)m0 * 1024, g_c1 + (size_t)m0 * 1024,
        g_wo0 + (size_t)n0 * 1024, g_wo1 + (size_t)n0 * 1024, acc);

    const int tid = threadIdx.x, lane = tid & 31, wid = tid >> 5;
    const int wr = wid >> 2, wc = wid & 3;

    #pragma unroll
    for (int mt = 0; mt < 4; mt++)
        #pragma unroll
        for (int nt = 0; nt < 4; nt++) {
            int f = n0 + wc * 32 + nt * 8 + (lane & 3) * 2;
            float bz0 = bo[f], bz1 = bo[f + 1];
            #pragma unroll
            for (int half = 0; half < 2; half++) {
                int m = m0 + wr * 64 + mt * 16 + (lane >> 2) + half * 8;
                float2 v;
                v.x = acc[mt][nt][half * 2 + 0] + bz0;
                v.y = acc[mt][nt][half * 2 + 1] + bz1;
                *(float2*)&out[(size_t)m * 1024 + f] = v;
            }
        }
}

// ---------------------------------------------------------------------------
extern "C" void kernel_launch(void* const* d_in, const int* in_sizes, int n_in,
                              void* d_out, int out_size)
{
    (void)in_sizes; (void)n_in; (void)out_size;
    const float* x     = (const float*)d_in[0];
    const float* noise = (const float*)d_in[1];
    const float* Wq    = (const float*)d_in[2];
    const float* bq    = (const float*)d_in[3];
    const float* Wk    = (const float*)d_in[4];
    const float* bk    = (const float*)d_in[5];
    const float* Wv    = (const float*)d_in[6];
    const float* bv    = (const float*)d_in[7];
    const float* Wo    = (const float*)d_in[8];
    const float* bo    = (const float*)d_in[9];
    const float* theta = (const float*)d_in[10];
    // d_in[11] = corr_w: unused (per-head bias cancels in softmax)
    float* out = (float*)d_out;

    cudaFuncSetAttribute(flash_kernel,
        cudaFuncAttributeMaxDynamicSharedMemorySize, FL_SMEM);

    split2_kernel<<<1024, 256>>>(x,  0, 0,       4194304);
    split2_kernel<<<512,  256>>>(Wq, 1, 0,       1048576);
    split2_kernel<<<512,  256>>>(Wk, 1, 1048576, 1048576);
    split2_kernel<<<512,  256>>>(Wv, 1, 2097152, 1048576);
    split2_kernel<<<512,  256>>>(Wo, 2, 0,       1048576);

    qkv_mma_kernel<<<dim3(32, 24), 256>>>(bq, bk, bv);
    flash_kernel<<<dim3(8, 64), 256, FL_SMEM>>>(noise, theta);
    outproj_mma_kernel<<<dim3(32, 8), 256>>>(bo, out);
}

// round 7
// speedup vs baseline: 3.1958x; 1.3217x over previous
#include <cuda_runtime.h>
#include <cuda_bf16.h>
#include <cstdint>
#include <math.h>

// Problem: B=4, H=16, T=1024, D=64, E=1024, M=B*T=4096, BH=64
// GEMMs are TN (C[m,n] = sum_k A[m,k]*B[n,k]) on bf16x2 split planes.

// ---------------------------------------------------------------------------
// Device-global scratch
// ---------------------------------------------------------------------------
__device__ __nv_bfloat16 g_xs0[4194304], g_xs1[4194304];   // x split   [4096][1024]
__device__ __nv_bfloat16 g_wb0[3145728], g_wb1[3145728];   // Wq|Wk|Wv  [3072][1024]
__device__ __nv_bfloat16 g_wo0[1048576], g_wo1[1048576];   // Wo        [1024][1024]
__device__ __nv_bfloat16 g_q0[4194304],  g_q1[4194304];    // q (pre-scaled 1/8) [bh][t][d]
__device__ __nv_bfloat16 g_k0[4194304],  g_k1[4194304];    // k  [bh][s][d]
__device__ __nv_bfloat16 g_vt0[4194304], g_vt1[4194304];   // vT [bh][d][s]
__device__ __nv_bfloat16 g_c0[4194304],  g_c1[4194304];    // ctx planes [m][e]

// ---------------------------------------------------------------------------
// PTX helpers
// ---------------------------------------------------------------------------
__device__ __forceinline__ uint32_t smem_u32(const void* p) {
    uint32_t a;
    asm("{ .reg .u64 t; cvta.to.shared.u64 t, %1; cvt.u32.u64 %0, t; }" : "=r"(a) : "l"(p));
    return a;
}

__device__ __forceinline__ void ldsm4(uint32_t r[4], uint32_t addr) {
    asm volatile("ldmatrix.sync.aligned.m8n8.x4.shared.b16 {%0,%1,%2,%3}, [%4];"
        : "=r"(r[0]), "=r"(r[1]), "=r"(r[2]), "=r"(r[3]) : "r"(addr));
}

__device__ __forceinline__ void mma_bf16(float* c, const uint32_t* a, const uint32_t* b) {
    asm volatile(
        "mma.sync.aligned.m16n8k16.row.col.f32.bf16.bf16.f32 "
        "{%0,%1,%2,%3}, {%4,%5,%6,%7}, {%8,%9}, {%0,%1,%2,%3};\n"
        : "+f"(c[0]), "+f"(c[1]), "+f"(c[2]), "+f"(c[3])
        : "r"(a[0]), "r"(a[1]), "r"(a[2]), "r"(a[3]), "r"(b[0]), "r"(b[1]));
}

#define CP16(dst, src) \
    asm volatile("cp.async.cg.shared.global [%0], [%1], 16;" :: "r"(dst), "l"(src))
#define CP_COMMIT() asm volatile("cp.async.commit_group;")
#define CP_WAIT(N)  asm volatile("cp.async.wait_group %0;" :: "n"(N))

__device__ __forceinline__ uint32_t pack_hi(float x, float y, float& rx, float& ry) {
    __nv_bfloat162 h;
    h.x = __float2bfloat16(x); h.y = __float2bfloat16(y);
    rx = x - __bfloat162float(h.x);
    ry = y - __bfloat162float(h.y);
    return *(uint32_t*)&h;
}
__device__ __forceinline__ uint32_t pack_bf2(float x, float y) {
    __nv_bfloat162 h;
    h.x = __float2bfloat16(x); h.y = __float2bfloat16(y);
    return *(uint32_t*)&h;
}

// ---------------------------------------------------------------------------
// Single merged split kernel: fp32 -> (hi, lo) bf16 planes, float4 vectorized.
// ---------------------------------------------------------------------------
__global__ __launch_bounds__(256) void split_all_kernel(
    const float* __restrict__ x,  const float* __restrict__ Wq,
    const float* __restrict__ Wk, const float* __restrict__ Wv,
    const float* __restrict__ Wo)
{
    const int NX = 1048576;   // x float4 count
    const int NW = 262144;    // per-weight float4 count
    const int NT = NX + 4 * NW;
    for (int i4 = blockIdx.x * 256 + threadIdx.x; i4 < NT; i4 += gridDim.x * 256) {
        const float* src; __nv_bfloat16 *d0, *d1; int idx;
        if (i4 < NX) { src = x; d0 = g_xs0; d1 = g_xs1; idx = i4; }
        else {
            int r = i4 - NX; int w = r / NW; idx = r - w * NW;
            if (w == 0)      { src = Wq; d0 = g_wb0;           d1 = g_wb1; }
            else if (w == 1) { src = Wk; d0 = g_wb0 + 1048576; d1 = g_wb1 + 1048576; }
            else if (w == 2) { src = Wv; d0 = g_wb0 + 2097152; d1 = g_wb1 + 2097152; }
            else             { src = Wo; d0 = g_wo0;           d1 = g_wo1; }
        }
        float4 a = ((const float4*)src)[idx];
        float r0, r1, r2, r3;
        uint32_t h01 = pack_hi(a.x, a.y, r0, r1);
        uint32_t h23 = pack_hi(a.z, a.w, r2, r3);
        uint32_t l01 = pack_bf2(r0, r1);
        uint32_t l23 = pack_bf2(r2, r3);
        uint2 vh; vh.x = h01; vh.y = h23;
        uint2 vl; vl.x = l01; vl.y = l23;
        *(uint2*)(d0 + 4 * (size_t)idx) = vh;
        *(uint2*)(d1 + 4 * (size_t)idx) = vl;
    }
}

// ---------------------------------------------------------------------------
// Core 128x128 tile GEMM (TN), bf16x2 3-pass, fp32 acc.
// cp.async 3-stage pipeline. Dynamic smem 73728 B:
//   A[stage][plane] at (s*2+p)*6144, B at 36864 + (s*2+p)*6144.
// ---------------------------------------------------------------------------
#define GP_SMEM 73728

template<int KSTEPS, int LDA, int LDB>
__device__ __forceinline__ void gemm128_pipe(
    char* smem,
    const __nv_bfloat16* __restrict__ A0, const __nv_bfloat16* __restrict__ A1,
    const __nv_bfloat16* __restrict__ B0, const __nv_bfloat16* __restrict__ B1,
    float acc[4][4][4])
{
    const int tid = threadIdx.x;
    const int lane = tid & 31;
    const int wid = tid >> 5;
    const int wr = wid >> 2;
    const int wc = wid & 3;
    const int lrow = tid >> 1;
    const int lc = tid & 1;
    uint32_t sb = smem_u32(smem);

    #pragma unroll
    for (int mt = 0; mt < 4; mt++)
        #pragma unroll
        for (int nt = 0; nt < 4; nt++)
            #pragma unroll
            for (int j = 0; j < 4; j++) acc[mt][nt][j] = 0.f;

    const char* srcA0 = (const char*)(A0 + (size_t)lrow * LDA) + lc * 16;
    const char* srcA1 = (const char*)(A1 + (size_t)lrow * LDA) + lc * 16;
    const char* srcB0 = (const char*)(B0 + (size_t)lrow * LDB) + lc * 16;
    const char* srcB1 = (const char*)(B1 + (size_t)lrow * LDB) + lc * 16;
    const uint32_t drow = lrow * 48 + lc * 16;

    auto issue = [&](int ks) {
        int s = ks % 3;
        size_t o = (size_t)ks * 32;
        CP16(sb + (s * 2 + 0) * 6144 + drow, srcA0 + o);
        CP16(sb + (s * 2 + 1) * 6144 + drow, srcA1 + o);
        CP16(sb + 36864 + (s * 2 + 0) * 6144 + drow, srcB0 + o);
        CP16(sb + 36864 + (s * 2 + 1) * 6144 + drow, srcB1 + o);
    };

    uint32_t aaddr[4];
    #pragma unroll
    for (int mt = 0; mt < 4; mt++)
        aaddr[mt] = sb + (uint32_t)((wr * 64 + mt * 16 + (lane & 15)) * 48 + (lane >> 4) * 16);

    const uint32_t brow = wc * 32 + (lane >> 2);
    const uint32_t bbase = sb + 36864 + brow * 48 + (lane & 3) * 4;

    issue(0); CP_COMMIT();
    issue(1); CP_COMMIT();

    for (int ks = 0; ks < KSTEPS; ks++) {
        const uint32_t soff = (uint32_t)(ks % 3) * 12288;
        CP_WAIT(1);
        __syncthreads();
        if (ks + 2 < KSTEPS) issue(ks + 2);
        CP_COMMIT();

        uint32_t aH[4][4], aL[4][4], bH[4][2], bL[4][2];
        #pragma unroll
        for (int mt = 0; mt < 4; mt++) {
            ldsm4(aH[mt], aaddr[mt] + soff);
            ldsm4(aL[mt], aaddr[mt] + soff + 6144);
        }
        #pragma unroll
        for (int nt = 0; nt < 4; nt++) {
            uint32_t b0 = bbase + soff + nt * 384;
            asm volatile("ld.shared.b32 %0, [%1];"      : "=r"(bH[nt][0]) : "r"(b0));
            asm volatile("ld.shared.b32 %0, [%1+16];"   : "=r"(bH[nt][1]) : "r"(b0));
            asm volatile("ld.shared.b32 %0, [%1+6144];" : "=r"(bL[nt][0]) : "r"(b0));
            asm volatile("ld.shared.b32 %0, [%1+6160];" : "=r"(bL[nt][1]) : "r"(b0));
        }
        #pragma unroll
        for (int mt = 0; mt < 4; mt++)
            #pragma unroll
            for (int nt = 0; nt < 4; nt++) {
                mma_bf16(acc[mt][nt], aH[mt], bH[nt]);
                mma_bf16(acc[mt][nt], aH[mt], bL[nt]);
                mma_bf16(acc[mt][nt], aL[mt], bH[nt]);
            }
    }
}

// ---------------------------------------------------------------------------
// QKV projection. grid (32, 24). q is pre-scaled by 0.125 (exact pow2).
// ---------------------------------------------------------------------------
__global__ __launch_bounds__(256) void qkv_mma_kernel(
    const float* __restrict__ bq, const float* __restrict__ bk,
    const float* __restrict__ bv)
{
    extern __shared__ char smem[];
    const int m0 = blockIdx.x * 128;
    const int n0 = blockIdx.y * 128;
    float acc[4][4][4];
    gemm128_pipe<64, 1024, 1024>(smem,
        g_xs0 + (size_t)m0 * 1024, g_xs1 + (size_t)m0 * 1024,
        g_wb0 + (size_t)n0 * 1024, g_wb1 + (size_t)n0 * 1024, acc);

    const int which = n0 >> 10;
    const int fbase = n0 & 1023;
    const float* bias = (which == 0) ? bq : (which == 1) ? bk : bv;
    const float psc = (which == 0) ? 0.125f : 1.0f;

    const int tid = threadIdx.x, lane = tid & 31, wid = tid >> 5;
    const int wr = wid >> 2, wc = wid & 3;

    #pragma unroll
    for (int mt = 0; mt < 4; mt++) {
        #pragma unroll
        for (int nt = 0; nt < 4; nt++) {
            int f = fbase + wc * 32 + nt * 8 + (lane & 3) * 2;
            int h = f >> 6, d = f & 63;
            float bz0 = bias[f], bz1 = bias[f + 1];
            #pragma unroll
            for (int half = 0; half < 2; half++) {
                int m = m0 + wr * 64 + mt * 16 + (lane >> 2) + half * 8;
                int b = m >> 10, t = m & 1023;
                float v0 = (acc[mt][nt][half * 2 + 0] + bz0) * psc;
                float v1 = (acc[mt][nt][half * 2 + 1] + bz1) * psc;
                __nv_bfloat16 h0 = __float2bfloat16(v0);
                __nv_bfloat16 h1 = __float2bfloat16(v1);
                __nv_bfloat16 l0 = __float2bfloat16(v0 - __bfloat162float(h0));
                __nv_bfloat16 l1 = __float2bfloat16(v1 - __bfloat162float(h1));
                if (which < 2) {
                    size_t idx = (((size_t)(b * 16 + h)) * 1024 + t) * 64 + d;
                    __nv_bfloat162 ph; ph.x = h0; ph.y = h1;
                    __nv_bfloat162 pl; pl.x = l0; pl.y = l1;
                    if (which == 0) {
                        *(__nv_bfloat162*)&g_q0[idx] = ph;
                        *(__nv_bfloat162*)&g_q1[idx] = pl;
                    } else {
                        *(__nv_bfloat162*)&g_k0[idx] = ph;
                        *(__nv_bfloat162*)&g_k1[idx] = pl;
                    }
                } else {
                    size_t base = ((size_t)(b * 16 + h) * 64 + d) * 1024 + t;
                    g_vt0[base] = h0;        g_vt1[base] = l0;
                    g_vt0[base + 1024] = h1; g_vt1[base + 1024] = l1;
                }
            }
        }
    }
}

// ---------------------------------------------------------------------------
// Fused flash attention with cp.async double-buffered K/V. grid (8, 64).
// ---------------------------------------------------------------------------
#define FQ0 0
#define FQ1 18432
#define FKV 36864
#define FKV_STRIDE 71680
#define FK1_OFF 18432
#define FV0_OFF 36864
#define FV1_OFF 54272
#define FL_SMEM (36864 + 2*71680)

__global__ __launch_bounds__(256) void flash_kernel(
    const float* __restrict__ noise, const float* __restrict__ theta)
{
    extern __shared__ char sm[];
    __nv_bfloat16* q0s = (__nv_bfloat16*)(sm + FQ0);
    __nv_bfloat16* q1s = (__nv_bfloat16*)(sm + FQ1);
    uint32_t sb = smem_u32(sm);

    const int tid = threadIdx.x;
    const int lane = tid & 31;
    const int wid = tid >> 5;
    const int m0 = blockIdx.x * 128;
    const int bh = blockIdx.y;
    const int bb = bh >> 4, hh = bh & 15;

    const char* gk0 = (const char*)(g_k0 + (size_t)bh * 65536);
    const char* gk1 = (const char*)(g_k1 + (size_t)bh * 65536);
    const char* gv0 = (const char*)(g_vt0 + (size_t)bh * 65536);
    const char* gv1 = (const char*)(g_vt1 + (size_t)bh * 65536);

    auto issue = [&](int s0, int b) {
        uint32_t base = sb + FKV + (uint32_t)b * FKV_STRIDE;
        #pragma unroll
        for (int j = 0; j < 4; j++) {
            int idx = j * 256 + tid;       // 0..1023
            int row = idx >> 3, c = idx & 7;
            CP16(base + row * 144 + c * 16,
                 gk0 + (size_t)(s0 + row) * 128 + c * 16);
            CP16(base + FK1_OFF + row * 144 + c * 16,
                 gk1 + (size_t)(s0 + row) * 128 + c * 16);
            int vrow = idx >> 4, vc = idx & 15;
            CP16(base + FV0_OFF + vrow * 272 + vc * 16,
                 gv0 + (size_t)vrow * 2048 + (size_t)s0 * 2 + vc * 16);
            CP16(base + FV1_OFF + vrow * 272 + vc * 16,
                 gv1 + (size_t)vrow * 2048 + (size_t)s0 * 2 + vc * 16);
        }
    };

    issue(0, 0); CP_COMMIT();

    // T_mean from theta (exact math: sinf/expf)
    float Tm = 0.f;
    #pragma unroll
    for (int h = 0; h < 16; h++) {
        float sg = 1.f / (1.f + expf(-theta[h]));
        Tm += fabsf(sinf(2.f * sg * 1.57079632679489662f));
    }
    Tm *= (1.f / 16.f);
    const float inv_keep = 1.f / (1.f - Tm + 1e-8f);

    // Load Q tile (resident for the whole kernel)
    {
        const __nv_bfloat16* gq0 = g_q0 + (size_t)bh * 65536 + (size_t)m0 * 64;
        const __nv_bfloat16* gq1 = g_q1 + (size_t)bh * 65536 + (size_t)m0 * 64;
        #pragma unroll
        for (int i = 0; i < 4; i++) {
            int idx = i * 256 + tid;
            int row = idx >> 3, c = idx & 7;
            *(float4*)(q0s + row * 72 + c * 8) = *(const float4*)(gq0 + row * 64 + c * 8);
            *(float4*)(q1s + row * 72 + c * 8) = *(const float4*)(gq1 + row * 64 + c * 8);
        }
    }

    uint32_t qa0 = smem_u32(q0s + (wid * 16 + (lane & 15)) * 72 + (lane >> 4) * 8);
    uint32_t qa1 = smem_u32(q1s + (wid * 16 + (lane & 15)) * 72 + (lane >> 4) * 8);

    // b-fragment base offsets — MUST include sb (bug fixed from R6)
    const uint32_t kfrag = sb + FKV + (lane >> 2) * 144 + (lane & 3) * 4;
    const uint32_t vfrag = sb + FKV + FV0_OFF + (lane >> 2) * 272 + (lane & 3) * 4;

    const int row_q = wid * 16 + (lane >> 2);
    const float* nz_base = noise + (size_t)bh * 1048576
                         + (size_t)(m0 + row_q) * 1024 + (lane & 3) * 2;

    float m_prev0 = -1e30f, m_prev1 = -1e30f;
    float l0 = 0.f, l1 = 0.f;
    float O[8][4];
    #pragma unroll
    for (int nt = 0; nt < 8; nt++)
        #pragma unroll
        for (int j = 0; j < 4; j++) O[nt][j] = 0.f;

    for (int it = 0; it < 8; it++) {
        const int s0 = it * 128;
        const int buf = it & 1;
        CP_WAIT(0);
        __syncthreads();
        if (it + 1 < 8) issue(s0 + 128, buf ^ 1);
        CP_COMMIT();

        const uint32_t kb0 = kfrag + (uint32_t)buf * FKV_STRIDE;
        const uint32_t vb0 = vfrag + (uint32_t)buf * FKV_STRIDE;

        // ---- scores: S(16x128) = Qw @ K^T ----
        float Sa[16][4];
        #pragma unroll
        for (int nt = 0; nt < 16; nt++)
            #pragma unroll
            for (int j = 0; j < 4; j++) Sa[nt][j] = 0.f;

        #pragma unroll
        for (int kc = 0; kc < 4; kc++) {
            uint32_t aH[4], aL[4];
            ldsm4(aH, qa0 + kc * 32);
            ldsm4(aL, qa1 + kc * 32);
            #pragma unroll
            for (int nt = 0; nt < 16; nt++) {
                uint32_t bHf[2], bLf[2];
                uint32_t a0 = kb0 + nt * 1152 + kc * 32;
                asm volatile("ld.shared.b32 %0, [%1];"       : "=r"(bHf[0]) : "r"(a0));
                asm volatile("ld.shared.b32 %0, [%1+16];"    : "=r"(bHf[1]) : "r"(a0));
                asm volatile("ld.shared.b32 %0, [%1+18432];" : "=r"(bLf[0]) : "r"(a0));
                asm volatile("ld.shared.b32 %0, [%1+18448];" : "=r"(bLf[1]) : "r"(a0));
                mma_bf16(Sa[nt], aH, bHf);
                mma_bf16(Sa[nt], aH, bLf);
                mma_bf16(Sa[nt], aL, bHf);
            }
        }

        // ---- online softmax ----
        float mt0 = -1e30f, mt1 = -1e30f;
        #pragma unroll
        for (int nt = 0; nt < 16; nt++) {
            mt0 = fmaxf(mt0, fmaxf(Sa[nt][0], Sa[nt][1]));
            mt1 = fmaxf(mt1, fmaxf(Sa[nt][2], Sa[nt][3]));
        }
        mt0 = fmaxf(mt0, __shfl_xor_sync(0xffffffffu, mt0, 1));
        mt0 = fmaxf(mt0, __shfl_xor_sync(0xffffffffu, mt0, 2));
        mt1 = fmaxf(mt1, __shfl_xor_sync(0xffffffffu, mt1, 1));
        mt1 = fmaxf(mt1, __shfl_xor_sync(0xffffffffu, mt1, 2));

        float mn0 = fmaxf(m_prev0, mt0), mn1 = fmaxf(m_prev1, mt1);
        float f0 = __expf(m_prev0 - mn0), f1 = __expf(m_prev1 - mn1);
        m_prev0 = mn0; m_prev1 = mn1;
        l0 *= f0; l1 *= f1;
        #pragma unroll
        for (int nt = 0; nt < 8; nt++) {
            O[nt][0] *= f0; O[nt][1] *= f0;
            O[nt][2] *= f1; O[nt][3] *= f1;
        }

        float rs0 = 0.f, rs1 = 0.f;
        #pragma unroll
        for (int nt = 0; nt < 16; nt++) {
            Sa[nt][0] = __expf(Sa[nt][0] - mn0);
            Sa[nt][1] = __expf(Sa[nt][1] - mn0);
            Sa[nt][2] = __expf(Sa[nt][2] - mn1);
            Sa[nt][3] = __expf(Sa[nt][3] - mn1);
            rs0 += Sa[nt][0] + Sa[nt][1];
            rs1 += Sa[nt][2] + Sa[nt][3];
        }
        rs0 += __shfl_xor_sync(0xffffffffu, rs0, 1);
        rs0 += __shfl_xor_sync(0xffffffffu, rs0, 2);
        rs1 += __shfl_xor_sync(0xffffffffu, rs1, 1);
        rs1 += __shfl_xor_sync(0xffffffffu, rs1, 2);
        l0 += rs0; l1 += rs1;

        // ---- dropout (after denominator accumulation) ----
        const float* nz0 = nz_base + s0;
        #pragma unroll
        for (int nt = 0; nt < 16; nt++) {
            float2 a = *(const float2*)(nz0 + nt * 8);
            float2 b = *(const float2*)(nz0 + 8192 + nt * 8);
            Sa[nt][0] *= (a.x > Tm) ? inv_keep : 0.f;
            Sa[nt][1] *= (a.y > Tm) ? inv_keep : 0.f;
            Sa[nt][2] *= (b.x > Tm) ? inv_keep : 0.f;
            Sa[nt][3] *= (b.y > Tm) ? inv_keep : 0.f;
        }

        // ---- P @ V ----
        #pragma unroll
        for (int kc = 0; kc < 8; kc++) {
            uint32_t aPH[4], aPL[4];
            float r0, r1;
            aPH[0] = pack_hi(Sa[2*kc][0],   Sa[2*kc][1],   r0, r1);
            aPL[0] = pack_bf2(r0, r1);
            aPH[1] = pack_hi(Sa[2*kc][2],   Sa[2*kc][3],   r0, r1);
            aPL[1] = pack_bf2(r0, r1);
            aPH[2] = pack_hi(Sa[2*kc+1][0], Sa[2*kc+1][1], r0, r1);
            aPL[2] = pack_bf2(r0, r1);
            aPH[3] = pack_hi(Sa[2*kc+1][2], Sa[2*kc+1][3], r0, r1);
            aPL[3] = pack_bf2(r0, r1);
            #pragma unroll
            for (int nt = 0; nt < 8; nt++) {
                uint32_t vH[2], vL[2];
                uint32_t a0 = vb0 + nt * 2176 + kc * 32;
                asm volatile("ld.shared.b32 %0, [%1];"       : "=r"(vH[0]) : "r"(a0));
                asm volatile("ld.shared.b32 %0, [%1+16];"    : "=r"(vH[1]) : "r"(a0));
                asm volatile("ld.shared.b32 %0, [%1+17408];" : "=r"(vL[0]) : "r"(a0));
                asm volatile("ld.shared.b32 %0, [%1+17424];" : "=r"(vL[1]) : "r"(a0));
                mma_bf16(O[nt], aPH, vH);
                mma_bf16(O[nt], aPH, vL);
                mma_bf16(O[nt], aPL, vH);
            }
        }
    }

    // ---- epilogue: normalize, split, write ctx planes [m][e] ----
    const float il0 = 1.f / l0, il1 = 1.f / l1;
    const int t0 = m0 + row_q;
    #pragma unroll
    for (int nt = 0; nt < 8; nt++) {
        int d = nt * 8 + (lane & 3) * 2;
        #pragma unroll
        for (int half = 0; half < 2; half++) {
            int t = t0 + half * 8;
            float v0 = O[nt][half * 2 + 0] * (half ? il1 : il0);
            float v1 = O[nt][half * 2 + 1] * (half ? il1 : il0);
            __nv_bfloat16 h0 = __float2bfloat16(v0);
            __nv_bfloat16 h1 = __float2bfloat16(v1);
            __nv_bfloat16 lo0 = __float2bfloat16(v0 - __bfloat162float(h0));
            __nv_bfloat16 lo1 = __float2bfloat16(v1 - __bfloat162float(h1));
            size_t idx = ((size_t)bb * 1024 + t) * 1024 + hh * 64 + d;
            __nv_bfloat162 ph; ph.x = h0; ph.y = h1;
            __nv_bfloat162 pl; pl.x = lo0; pl.y = lo1;
            *(__nv_bfloat162*)&g_c0[idx] = ph;
            *(__nv_bfloat162*)&g_c1[idx] = pl;
        }
    }
}

// ---------------------------------------------------------------------------
// Output projection. grid (32, 8). out = ctx @ Wo^T + bo (fp32 out).
// ---------------------------------------------------------------------------
__global__ __launch_bounds__(256) void outproj_mma_kernel(
    const float* __restrict__ bo, float* __restrict__ out)
{
    extern __shared__ char smem[];
    const int m0 = blockIdx.x * 128;
    const int n0 = blockIdx.y * 128;
    float acc[4][4][4];
    gemm128_pipe<64, 1024, 1024>(smem,
        g_c0 + (size_t)m0 * 1024, g_c1 + (size_t)m0 * 1024,
        g_wo0 + (size_t)n0 * 1024, g_wo1 + (size_t)n0 * 1024, acc);

    const int tid = threadIdx.x, lane = tid & 31, wid = tid >> 5;
    const int wr = wid >> 2, wc = wid & 3;

    #pragma unroll
    for (int mt = 0; mt < 4; mt++)
        #pragma unroll
        for (int nt = 0; nt < 4; nt++) {
            int f = n0 + wc * 32 + nt * 8 + (lane & 3) * 2;
            float bz0 = bo[f], bz1 = bo[f + 1];
            #pragma unroll
            for (int half = 0; half < 2; half++) {
                int m = m0 + wr * 64 + mt * 16 + (lane >> 2) + half * 8;
                float2 v;
                v.x = acc[mt][nt][half * 2 + 0] + bz0;
                v.y = acc[mt][nt][half * 2 + 1] + bz1;
                *(float2*)&out[(size_t)m * 1024 + f] = v;
            }
        }
}

// ---------------------------------------------------------------------------
extern "C" void kernel_launch(void* const* d_in, const int* in_sizes, int n_in,
                              void* d_out, int out_size)
{
    (void)in_sizes; (void)n_in; (void)out_size;
    const float* x     = (const float*)d_in[0];
    const float* noise = (const float*)d_in[1];
    const float* Wq    = (const float*)d_in[2];
    const float* bq    = (const float*)d_in[3];
    const float* Wk    = (const float*)d_in[4];
    const float* bk    = (const float*)d_in[5];
    const float* Wv    = (const float*)d_in[6];
    const float* bv    = (const float*)d_in[7];
    const float* Wo    = (const float*)d_in[8];
    const float* bo    = (const float*)d_in[9];
    const float* theta = (const float*)d_in[10];
    // d_in[11] = corr_w: unused (per-head bias cancels in softmax)
    float* out = (float*)d_out;

    cudaFuncSetAttribute(flash_kernel,
        cudaFuncAttributeMaxDynamicSharedMemorySize, FL_SMEM);
    cudaFuncSetAttribute(qkv_mma_kernel,
        cudaFuncAttributeMaxDynamicSharedMemorySize, GP_SMEM);
    cudaFuncSetAttribute(outproj_mma_kernel,
        cudaFuncAttributeMaxDynamicSharedMemorySize, GP_SMEM);

    split_all_kernel<<<4096, 256>>>(x, Wq, Wk, Wv, Wo);
    qkv_mma_kernel<<<dim3(32, 24), 256, GP_SMEM>>>(bq, bk, bv);
    flash_kernel<<<dim3(8, 64), 256, FL_SMEM>>>(noise, theta);
    outproj_mma_kernel<<<dim3(32, 8), 256, GP_SMEM>>>(bo, out);
}